// round 3
// baseline (speedup 1.0000x reference)
#include <cuda_runtime.h>
#include <cuda_bf16.h>

// Fixed problem shapes:
//   tex (8,16,512,512) f32, iuv (8,3,512,512) i32, lut (24,256,256,2) f32,
//   tex_res = 512 (1-element i32 device scalar), out (8,16,512,512) f32.
#define BB 8
#define CC 16
#define RR 512
#define RR2 (RR * RR)        // 2^18
#define HW  (512 * 512)      // 2^18
#define LOG2_RR2 18
#define LOG2_HW  18
#define NB 2                 // batches per chunk
#define CHUNK_ELEMS ((size_t)NB * RR2 * CC)   // 8M floats = 32 MiB

// Double-buffered transposed-tex scratch: [buf][bl][pixel][channel].
// 2 x 32 MiB, both L2-resident; streaming traffic uses .cs (evict-first)
// so these lines stay hot and (nearly) never touch DRAM.
__device__ float g_scratch[2 * CHUNK_ELEMS];

// ---------------------------------------------------------------------------
// Fused step kernel. Blocks [0, dp_blocks): gather chunk b0_dp from buf_dp.
// Blocks [dp_blocks, ...): transpose chunk b0_tr into buf_tr.
// The two roles are data-independent; running them in one launch overlaps
// the transpose's DRAM streaming with the gather's L2-latency stalls.
// ---------------------------------------------------------------------------
__global__ void __launch_bounds__(256) fused_kernel(
    const float* __restrict__ tex,
    const int*   __restrict__ iuv,
    const float* __restrict__ lut,
    const int*   __restrict__ tex_res_ptr,
    float*       __restrict__ out,
    int dp_blocks, int b0_dp, int buf_dp, int b0_tr, int buf_tr)
{
    if ((int)blockIdx.x < dp_blocks) {
        // ---------------- densepose gather: 2 pixels per thread -----------
        int t   = blockIdx.x * 256 + threadIdx.x;      // [0, NB*HW/2)
        int pp  = t & (HW / 2 - 1);
        int bl  = t >> (LOG2_HW - 1);                  // local batch
        int pix = pp * 2;
        int b   = b0_dp + bl;

        const float* scr = g_scratch + (size_t)buf_dp * CHUNK_ELEMS
                                     + (size_t)bl * RR2 * CC;

        const int* base = iuv + (size_t)b * 3 * HW + pix;
        int2 part = __ldcs(reinterpret_cast<const int2*>(base));
        int2 u8   = __ldcs(reinterpret_cast<const int2*>(base + HW));
        int2 v8   = __ldcs(reinterpret_cast<const int2*>(base + 2 * HW));
        float resm1 = (float)(__ldg(tex_res_ptr) - 1);

        float4 g[2][4];
        #pragma unroll
        for (int k = 0; k < 2; k++) {
            int p_ = k ? part.y : part.x;
            int uu = k ? u8.y   : u8.x;
            int vv = k ? v8.y   : v8.x;

            int i = min(max(p_ - 1, 0), 23);
            // Replicate reference float math exactly (rn = half-to-even).
            float uf = fminf(fmaxf((float)uu * (1.0f / 255.0f), 0.0f), 1.0f);
            float vf = fminf(fmaxf((float)vv * (1.0f / 255.0f), 0.0f), 1.0f);
            int ui = __float2int_rn(uf * 255.0f);
            int vi = __float2int_rn(vf * 255.0f);

            float2 uv = __ldg(reinterpret_cast<const float2*>(lut)
                              + ((size_t)i * 256 + vi) * 256 + ui);

            int u_I = min(max(__float2int_rn(uv.x * resm1), 0), RR - 1);
            int v_I = min(max(__float2int_rn((1.0f - uv.y) * resm1), 0), RR - 1);

            const float4* s = reinterpret_cast<const float4*>(scr)
                            + ((size_t)v_I * RR + u_I) * 4;
            g[k][0] = __ldg(s + 0);
            g[k][1] = __ldg(s + 1);
            g[k][2] = __ldg(s + 2);
            g[k][3] = __ldg(s + 3);
            if (p_ <= 0) {
                g[k][0] = g[k][1] = g[k][2] = g[k][3]
                        = make_float4(0.f, 0.f, 0.f, 0.f);
            }
        }

        // 16 channel stores, float2 each (2 consecutive pixels), coalesced.
        float* o = out + (size_t)b * CC * HW + pix;
        #pragma unroll
        for (int c = 0; c < 16; c++) {
            float2 w;
            w.x = reinterpret_cast<const float*>(&g[0][c >> 2])[c & 3];
            w.y = reinterpret_cast<const float*>(&g[1][c >> 2])[c & 3];
            __stcs(reinterpret_cast<float2*>(o + (size_t)c * HW), w);
        }
    } else {
        // ---------------- transpose: 1 pixel (16 channels) per thread -----
        int t  = (blockIdx.x - dp_blocks) * 256 + threadIdx.x; // [0, NB*RR2)
        int p  = t & (RR2 - 1);
        int bl = t >> LOG2_RR2;
        int b  = b0_tr + bl;

        const float* src = tex + (size_t)b * CC * RR2 + p;
        float v[16];
        #pragma unroll
        for (int c = 0; c < 16; c++)
            v[c] = __ldcs(src + (size_t)c * RR2);

        float4* dst = reinterpret_cast<float4*>(
                          g_scratch + (size_t)buf_tr * CHUNK_ELEMS)
                    + ((size_t)bl * RR2 + p) * 4;
        dst[0] = make_float4(v[ 0], v[ 1], v[ 2], v[ 3]);
        dst[1] = make_float4(v[ 4], v[ 5], v[ 6], v[ 7]);
        dst[2] = make_float4(v[ 8], v[ 9], v[10], v[11]);
        dst[3] = make_float4(v[12], v[13], v[14], v[15]);
    }
}

extern "C" void kernel_launch(void* const* d_in, const int* in_sizes, int n_in,
                              void* d_out, int out_size)
{
    const float* tex     = (const float*)d_in[0];
    const int*   iuv     = (const int*)  d_in[1];
    const float* lut     = (const float*)d_in[2];
    const int*   tex_res = (const int*)  d_in[3];
    float* out = (float*)d_out;

    const int DP_BLOCKS = (NB * HW / 2) / 256;   // 1024
    const int TR_BLOCKS = (NB * RR2)    / 256;   // 2048
    const int NCHUNK    = BB / NB;               // 4

    // Prologue: transpose chunk 0 into buf 0.
    fused_kernel<<<TR_BLOCKS, 256>>>(tex, iuv, lut, tex_res, out,
                                     /*dp_blocks=*/0, 0, 0,
                                     /*b0_tr=*/0, /*buf_tr=*/0);
    // Steady state: gather chunk k (buf k%2) + transpose chunk k+1 (buf (k+1)%2).
    for (int k = 0; k < NCHUNK - 1; k++) {
        fused_kernel<<<DP_BLOCKS + TR_BLOCKS, 256>>>(
            tex, iuv, lut, tex_res, out,
            DP_BLOCKS, /*b0_dp=*/k * NB, /*buf_dp=*/k & 1,
            /*b0_tr=*/(k + 1) * NB, /*buf_tr=*/(k + 1) & 1);
    }
    // Epilogue: gather last chunk.
    fused_kernel<<<DP_BLOCKS, 256>>>(tex, iuv, lut, tex_res, out,
                                     DP_BLOCKS, (NCHUNK - 1) * NB,
                                     (NCHUNK - 1) & 1,
                                     /*b0_tr=*/0, /*buf_tr=*/0);
}